// round 16
// baseline (speedup 1.0000x reference)
#include <cuda_runtime.h>

#define NMAX 100000

// Aggregation buffer agg[dst] = sum_e w_e * x_src[src_e]; 25.6 MB static.
// Zero-initialized at module load; the fused GEMM re-zeroes each row after
// consuming it, so the zero-invariant holds across graph replays (no memset).
static __device__ __align__(16) float g_agg[NMAX * 64];

// ---------------------------------------------------------------------------
// Edge scatter (input space): g_agg[dst] += x_src[src] * w.
// PROVEN 65us structure (REDG lane-rate floor): folded dtype detect,
// 8 edges/thread, 16 lanes/edge, v4 REDs, no dynamic smem.
// ---------------------------------------------------------------------------
__global__ void __launch_bounds__(256) scatter_kernel(
    const float* __restrict__ xsrc,
    const void* __restrict__ ei_raw,    // [2, E]: src row then dst row
    const float* __restrict__ ew,       // [E]
    int E, int n_src)
{
    // dtype detect (JAX demotes int64->int32 when x64 off): warp 0 samples
    // 32 int64 slots (in-bounds under both layouts); int32 pairs have random
    // high words -> out of [0, n_src).
    __shared__ int sflag;
    {
        const long long* ei = (const long long*)ei_raw;
        if (threadIdx.x < 32) {
            long long stride = (E > 32) ? (E / 32) : 1;
            long long idx = (long long)threadIdx.x * stride;
            if (idx > E - 1) idx = E - 1;
            long long v = ei[idx];
            bool bad = (v < 0 || v >= n_src);
            unsigned m = __ballot_sync(0xffffffffu, bad);
            if (threadIdx.x == 0) sflag = (m == 0) ? 1 : 0;
        }
        __syncthreads();
    }
    const int is64 = sflag;

    const long long t = (long long)blockIdx.x * blockDim.x + threadIdx.x;
    const int lane = (int)(t & 15);
    const long long e0 = (t >> 4) * 8;
    if (e0 >= E) return;
    const int n = (E - e0 >= 8) ? 8 : (int)(E - e0);

    int s[8], d[8];
    float w[8];
    if (is64) {
        const long long* ei = (const long long*)ei_raw;
        #pragma unroll
        for (int i = 0; i < 8; i++) if (i < n) {
            s[i] = (int)ei[e0 + i];
            d[i] = (int)ei[(long long)E + e0 + i];
        }
    } else {
        const int* ei = (const int*)ei_raw;
        #pragma unroll
        for (int i = 0; i < 8; i++) if (i < n) {
            s[i] = ei[e0 + i];
            d[i] = ei[(long long)E + e0 + i];
        }
    }
    #pragma unroll
    for (int i = 0; i < 8; i++) if (i < n) w[i] = ew[e0 + i];

    float4 v[8];
    #pragma unroll
    for (int i = 0; i < 8; i++) if (i < n)
        v[i] = *(const float4*)(xsrc + (size_t)s[i] * 64 + lane * 4);

    #pragma unroll
    for (int i = 0; i < 8; i++) if (i < n) {
        const float wi = w[i];
        float4 vv = v[i];
        vv.x *= wi; vv.y *= wi; vv.z *= wi; vv.w *= wi;
        float* dst = g_agg + (size_t)d[i] * 64 + lane * 4;
        asm volatile("red.global.add.v4.f32 [%0], {%1, %2, %3, %4};"
                     :: "l"(dst), "f"(vv.x), "f"(vv.y), "f"(vv.z), "f"(vv.w)
                     : "memory");
    }
}

// ---------------------------------------------------------------------------
// tf32 helpers
// ---------------------------------------------------------------------------
__device__ __forceinline__ unsigned f2tf32(float x) {
    unsigned u;
    asm("cvt.rna.tf32.f32 %0, %1;" : "=r"(u) : "f"(x));
    return u;
}

#define MMA_TF32(c0, c1, c2, c3, a0, a1, a2, a3, b0, b1)                     \
    asm volatile(                                                            \
        "mma.sync.aligned.m16n8k8.row.col.f32.tf32.tf32.f32 "               \
        "{%0,%1,%2,%3}, {%4,%5,%6,%7}, {%8,%9}, {%0,%1,%2,%3};"             \
        : "+f"(c0), "+f"(c1), "+f"(c2), "+f"(c3)                             \
        : "r"(a0), "r"(a1), "r"(a2), "r"(a3), "r"(b0), "r"(b1))

// ---------------------------------------------------------------------------
// Fused tf32 GEMM (PROVEN round-9 24.9us structure):
//   out = x_dst @ W_self^T + g_agg @ W_nei^T + b    (N x 64)
// Register-prefetched A halves: As0 LDG before B staging; As1 LDG before
// MMA0 (in flight through it). After consuming As1 from registers, the same
// threads store zeros back to g_agg (same-address-after-load -> ordered),
// replacing the memset node.
// ---------------------------------------------------------------------------
#define AS_STRIDE 68
#define BS_STRIDE 132
#define AS_FLOATS (128 * AS_STRIDE)
#define BS_FLOATS (64 * BS_STRIDE)
#define GEMM_SMEM_BYTES ((AS_FLOATS + BS_FLOATS) * 4)

__global__ void __launch_bounds__(256) fused_gemm_tf32_kernel(
    const float* __restrict__ Xd, const float* __restrict__ Wself,
    const float* __restrict__ Wnei, const float* __restrict__ bias,
    float* __restrict__ out, int N)
{
    extern __shared__ __align__(16) float smem[];
    float* As = smem;                 // [128][AS_STRIDE]
    float* Bs = smem + AS_FLOATS;     // [64][BS_STRIDE]

    const int tid  = threadIdx.x;
    const int lane = tid & 31;
    const int wid  = tid >> 5;
    const int g    = lane >> 2;
    const int tg   = lane & 3;
    const int wr   = wid * 16;
    const int rowbase = blockIdx.x * 128;

    // Per-thread staging coordinates (8 float4 slots covering 128x64).
    int srow[8], sk4[8];
    bool sok[8];
    #pragma unroll
    for (int i = 0; i < 8; i++) {
        int f = tid + i * 256;
        srow[i] = f >> 4;
        sk4[i]  = f & 15;
        sok[i]  = (rowbase + srow[i]) < N;
    }

    // ---- issue As0 loads (x_dst) FIRST; flight hides behind B staging ----
    float4 areg[8];
    #pragma unroll
    for (int i = 0; i < 8; i++) {
        areg[i] = make_float4(0.f, 0.f, 0.f, 0.f);
        if (sok[i])
            areg[i] = *(const float4*)(Xd + (size_t)(rowbase + srow[i]) * 64 + sk4[i] * 4);
    }

    // ---- stage B (both W matrices), cvt to tf32 ----
    #pragma unroll
    for (int m = 0; m < 2; m++) {
        const float* Wm = m ? Wnei : Wself;
        #pragma unroll
        for (int i = 0; i < 4; i++) {
            int f  = tid + i * 256;
            int c  = f >> 4;
            int k4 = f & 15;
            float4 v = *(const float4*)(Wm + c * 64 + k4 * 4);
            float* b = Bs + c * BS_STRIDE + m * 64 + k4 * 4;
            b[0] = __uint_as_float(f2tf32(v.x));
            b[1] = __uint_as_float(f2tf32(v.y));
            b[2] = __uint_as_float(f2tf32(v.z));
            b[3] = __uint_as_float(f2tf32(v.w));
        }
    }

    // ---- store As0 to shared (cvt tf32) ----
    #pragma unroll
    for (int i = 0; i < 8; i++) {
        float4 cv;
        cv.x = __uint_as_float(f2tf32(areg[i].x));
        cv.y = __uint_as_float(f2tf32(areg[i].y));
        cv.z = __uint_as_float(f2tf32(areg[i].z));
        cv.w = __uint_as_float(f2tf32(areg[i].w));
        *(float4*)(As + srow[i] * AS_STRIDE + sk4[i] * 4) = cv;
    }

    // ---- accumulators init with bias ----
    float acc[8][4];
    #pragma unroll
    for (int nt = 0; nt < 8; nt++) {
        float b0 = bias[nt * 8 + 2 * tg];
        float b1 = bias[nt * 8 + 2 * tg + 1];
        acc[nt][0] = b0; acc[nt][1] = b1;
        acc[nt][2] = b0; acc[nt][3] = b1;
    }

    __syncthreads();

    // ---- issue As1 loads (agg); flight hides behind MMA0.
    //      Immediately store zeros back (same address, program-ordered
    //      after the load) -> agg is re-zeroed for the next replay. ----
    float* aggp = g_agg;
    #pragma unroll
    for (int i = 0; i < 8; i++) {
        float4 v = make_float4(0.f, 0.f, 0.f, 0.f);
        if (sok[i]) {
            float* ap = aggp + (size_t)(rowbase + srow[i]) * 64 + sk4[i] * 4;
            v = *(const float4*)ap;
            *(float4*)ap = make_float4(0.f, 0.f, 0.f, 0.f);
        }
        areg[i] = v;
    }

    // ---- MMA h=0 (x_dst @ W_self^T) ----
    #pragma unroll
    for (int kc = 0; kc < 8; kc++) {
        const int k0 = kc * 8;
        const float* arow0 = As + (wr + g) * AS_STRIDE + k0;
        const float* arow1 = arow0 + 8 * AS_STRIDE;
        unsigned a0 = __float_as_uint(arow0[tg]);
        unsigned a1 = __float_as_uint(arow1[tg]);
        unsigned a2 = __float_as_uint(arow0[tg + 4]);
        unsigned a3 = __float_as_uint(arow1[tg + 4]);
        #pragma unroll
        for (int nt = 0; nt < 8; nt++) {
            const float* brow = Bs + (nt * 8 + g) * BS_STRIDE + k0;
            unsigned b0 = __float_as_uint(brow[tg]);
            unsigned b1 = __float_as_uint(brow[tg + 4]);
            MMA_TF32(acc[nt][0], acc[nt][1], acc[nt][2], acc[nt][3],
                     a0, a1, a2, a3, b0, b1);
        }
    }

    __syncthreads();   // all warps done reading As0

    // ---- store As1 to shared (cvt tf32) ----
    #pragma unroll
    for (int i = 0; i < 8; i++) {
        float4 cv;
        cv.x = __uint_as_float(f2tf32(areg[i].x));
        cv.y = __uint_as_float(f2tf32(areg[i].y));
        cv.z = __uint_as_float(f2tf32(areg[i].z));
        cv.w = __uint_as_float(f2tf32(areg[i].w));
        *(float4*)(As + srow[i] * AS_STRIDE + sk4[i] * 4) = cv;
    }
    __syncthreads();

    // ---- MMA h=1 (agg @ W_nei^T) ----
    #pragma unroll
    for (int kc = 0; kc < 8; kc++) {
        const int k0 = kc * 8;
        const float* arow0 = As + (wr + g) * AS_STRIDE + k0;
        const float* arow1 = arow0 + 8 * AS_STRIDE;
        unsigned a0 = __float_as_uint(arow0[tg]);
        unsigned a1 = __float_as_uint(arow1[tg]);
        unsigned a2 = __float_as_uint(arow0[tg + 4]);
        unsigned a3 = __float_as_uint(arow1[tg + 4]);
        #pragma unroll
        for (int nt = 0; nt < 8; nt++) {
            const float* brow = Bs + (nt * 8 + g) * BS_STRIDE + 64 + k0;
            unsigned b0 = __float_as_uint(brow[tg]);
            unsigned b1 = __float_as_uint(brow[tg + 4]);
            MMA_TF32(acc[nt][0], acc[nt][1], acc[nt][2], acc[nt][3],
                     a0, a1, a2, a3, b0, b1);
        }
    }

    // ---- store ----
    const int r0 = rowbase + wr + g;
    const int r1 = r0 + 8;
    if (r0 < N) {
        float* yrow = out + (size_t)r0 * 64;
        #pragma unroll
        for (int nt = 0; nt < 8; nt++)
            *(float2*)(yrow + nt * 8 + 2 * tg) = make_float2(acc[nt][0], acc[nt][1]);
    }
    if (r1 < N) {
        float* yrow = out + (size_t)r1 * 64;
        #pragma unroll
        for (int nt = 0; nt < 8; nt++)
            *(float2*)(yrow + nt * 8 + 2 * tg) = make_float2(acc[nt][2], acc[nt][3]);
    }
}

// ---------------------------------------------------------------------------
// Inputs: 0:x_src f32[Ns*64] 1:x_dst f32[Nd*64] 2:edge_index[2E] (i32/i64)
//         3:edge_weight f32[E] 4:W_nei [64,64] 5:W_self [64,64] 6:b_self [64]
// Output: f32 [Nd*64]
// ---------------------------------------------------------------------------
extern "C" void kernel_launch(void* const* d_in, const int* in_sizes, int n_in,
                              void* d_out, int out_size)
{
    const float* x_src  = (const float*)d_in[0];
    const float* x_dst  = (const float*)d_in[1];
    const void*  ei     = d_in[2];
    const float* ew     = (const float*)d_in[3];
    const float* W_nei  = (const float*)d_in[4];
    const float* W_self = (const float*)d_in[5];
    const float* b_self = (const float*)d_in[6];
    float*       out    = (float*)d_out;

    const int n_src = in_sizes[0] / 64;
    const int n_dst = in_sizes[1] / 64;
    const int E     = in_sizes[3];

    cudaFuncSetAttribute(fused_gemm_tf32_kernel,
                         cudaFuncAttributeMaxDynamicSharedMemorySize,
                         GEMM_SMEM_BYTES);

    // 1) scatter in input space (agg starts zeroed: module-load init on the
    //    first call, GEMM self-zeroing on every subsequent call/replay)
    {
        long long groups  = ((long long)E + 7) / 8;
        long long threads = groups * 16;
        int blocks = (int)((threads + 255) / 256);
        scatter_kernel<<<blocks, 256>>>(x_src, ei, ew, E, n_src);
    }

    // 2) fused tf32 GEMM: out = x_dst @ W_self^T + agg @ W_nei^T + b
    //    (also re-zeroes agg)
    fused_gemm_tf32_kernel<<<(n_dst + 127) / 128, 256, GEMM_SMEM_BYTES>>>(
        x_dst, W_self, W_nei, b_self, out, n_dst);
}

// round 17
// speedup vs baseline: 1.1800x; 1.1800x over previous
#include <cuda_runtime.h>

#define NMAX 100000

// Aggregation buffer agg[dst] = sum_e w_e * x_src[src_e]; 25.6 MB static.
// Zero at module load; the fused GEMM re-zeroes consumed rows in a batched
// EPILOGUE (after all compute), so the zero-invariant holds across replays
// without a memset node.
static __device__ __align__(16) float g_agg[NMAX * 64];

// ---------------------------------------------------------------------------
// Edge scatter (input space): g_agg[dst] += x_src[src] * w.
// PROVEN 65us structure (REDG lane-rate floor): folded dtype detect,
// 8 edges/thread, 16 lanes/edge, v4 REDs, no dynamic smem. FROZEN.
// ---------------------------------------------------------------------------
__global__ void __launch_bounds__(256) scatter_kernel(
    const float* __restrict__ xsrc,
    const void* __restrict__ ei_raw,    // [2, E]: src row then dst row
    const float* __restrict__ ew,       // [E]
    int E, int n_src)
{
    // dtype detect (JAX demotes int64->int32 when x64 off): warp 0 samples
    // 32 int64 slots (in-bounds under both layouts); int32 pairs have random
    // high words -> out of [0, n_src).
    __shared__ int sflag;
    {
        const long long* ei = (const long long*)ei_raw;
        if (threadIdx.x < 32) {
            long long stride = (E > 32) ? (E / 32) : 1;
            long long idx = (long long)threadIdx.x * stride;
            if (idx > E - 1) idx = E - 1;
            long long v = ei[idx];
            bool bad = (v < 0 || v >= n_src);
            unsigned m = __ballot_sync(0xffffffffu, bad);
            if (threadIdx.x == 0) sflag = (m == 0) ? 1 : 0;
        }
        __syncthreads();
    }
    const int is64 = sflag;

    const long long t = (long long)blockIdx.x * blockDim.x + threadIdx.x;
    const int lane = (int)(t & 15);
    const long long e0 = (t >> 4) * 8;
    if (e0 >= E) return;
    const int n = (E - e0 >= 8) ? 8 : (int)(E - e0);

    int s[8], d[8];
    float w[8];
    if (is64) {
        const long long* ei = (const long long*)ei_raw;
        #pragma unroll
        for (int i = 0; i < 8; i++) if (i < n) {
            s[i] = (int)ei[e0 + i];
            d[i] = (int)ei[(long long)E + e0 + i];
        }
    } else {
        const int* ei = (const int*)ei_raw;
        #pragma unroll
        for (int i = 0; i < 8; i++) if (i < n) {
            s[i] = ei[e0 + i];
            d[i] = ei[(long long)E + e0 + i];
        }
    }
    #pragma unroll
    for (int i = 0; i < 8; i++) if (i < n) w[i] = ew[e0 + i];

    float4 v[8];
    #pragma unroll
    for (int i = 0; i < 8; i++) if (i < n)
        v[i] = *(const float4*)(xsrc + (size_t)s[i] * 64 + lane * 4);

    #pragma unroll
    for (int i = 0; i < 8; i++) if (i < n) {
        const float wi = w[i];
        float4 vv = v[i];
        vv.x *= wi; vv.y *= wi; vv.z *= wi; vv.w *= wi;
        float* dst = g_agg + (size_t)d[i] * 64 + lane * 4;
        asm volatile("red.global.add.v4.f32 [%0], {%1, %2, %3, %4};"
                     :: "l"(dst), "f"(vv.x), "f"(vv.y), "f"(vv.z), "f"(vv.w)
                     : "memory");
    }
}

// ---------------------------------------------------------------------------
// tf32 helpers
// ---------------------------------------------------------------------------
__device__ __forceinline__ unsigned f2tf32(float x) {
    unsigned u;
    asm("cvt.rna.tf32.f32 %0, %1;" : "=r"(u) : "f"(x));
    return u;
}

#define MMA_TF32(c0, c1, c2, c3, a0, a1, a2, a3, b0, b1)                     \
    asm volatile(                                                            \
        "mma.sync.aligned.m16n8k8.row.col.f32.tf32.tf32.f32 "               \
        "{%0,%1,%2,%3}, {%4,%5,%6,%7}, {%8,%9}, {%0,%1,%2,%3};"             \
        : "+f"(c0), "+f"(c1), "+f"(c2), "+f"(c3)                             \
        : "r"(a0), "r"(a1), "r"(a2), "r"(a3), "r"(b0), "r"(b1))

// ---------------------------------------------------------------------------
// Fused tf32 GEMM (PROVEN round-9 24.9us structure, UNMODIFIED load path):
//   out = x_dst @ W_self^T + g_agg @ W_nei^T + b    (N x 64)
// As0 LDG batch before B staging; As1 LDG batch (pure, MLP=8) before MMA0.
// NEW: batched zero-store epilogue to g_agg AFTER the output stores —
// program-ordered after the loads, zero interference with the load batches.
// ---------------------------------------------------------------------------
#define AS_STRIDE 68
#define BS_STRIDE 132
#define AS_FLOATS (128 * AS_STRIDE)
#define BS_FLOATS (64 * BS_STRIDE)
#define GEMM_SMEM_BYTES ((AS_FLOATS + BS_FLOATS) * 4)

__global__ void __launch_bounds__(256) fused_gemm_tf32_kernel(
    const float* __restrict__ Xd, const float* __restrict__ Wself,
    const float* __restrict__ Wnei, const float* __restrict__ bias,
    float* __restrict__ out, int N)
{
    extern __shared__ __align__(16) float smem[];
    float* As = smem;                 // [128][AS_STRIDE]
    float* Bs = smem + AS_FLOATS;     // [64][BS_STRIDE]

    const int tid  = threadIdx.x;
    const int lane = tid & 31;
    const int wid  = tid >> 5;
    const int g    = lane >> 2;
    const int tg   = lane & 3;
    const int wr   = wid * 16;
    const int rowbase = blockIdx.x * 128;

    // Per-thread staging coordinates (8 float4 slots covering 128x64).
    int srow[8], sk4[8];
    bool sok[8];
    #pragma unroll
    for (int i = 0; i < 8; i++) {
        int f = tid + i * 256;
        srow[i] = f >> 4;
        sk4[i]  = f & 15;
        sok[i]  = (rowbase + srow[i]) < N;
    }

    // ---- issue As0 loads (x_dst) FIRST; flight hides behind B staging ----
    float4 areg[8];
    #pragma unroll
    for (int i = 0; i < 8; i++) {
        areg[i] = make_float4(0.f, 0.f, 0.f, 0.f);
        if (sok[i])
            areg[i] = *(const float4*)(Xd + (size_t)(rowbase + srow[i]) * 64 + sk4[i] * 4);
    }

    // ---- stage B (both W matrices), cvt to tf32 ----
    #pragma unroll
    for (int m = 0; m < 2; m++) {
        const float* Wm = m ? Wnei : Wself;
        #pragma unroll
        for (int i = 0; i < 4; i++) {
            int f  = tid + i * 256;
            int c  = f >> 4;
            int k4 = f & 15;
            float4 v = *(const float4*)(Wm + c * 64 + k4 * 4);
            float* b = Bs + c * BS_STRIDE + m * 64 + k4 * 4;
            b[0] = __uint_as_float(f2tf32(v.x));
            b[1] = __uint_as_float(f2tf32(v.y));
            b[2] = __uint_as_float(f2tf32(v.z));
            b[3] = __uint_as_float(f2tf32(v.w));
        }
    }

    // ---- store As0 to shared (cvt tf32) ----
    #pragma unroll
    for (int i = 0; i < 8; i++) {
        float4 cv;
        cv.x = __uint_as_float(f2tf32(areg[i].x));
        cv.y = __uint_as_float(f2tf32(areg[i].y));
        cv.z = __uint_as_float(f2tf32(areg[i].z));
        cv.w = __uint_as_float(f2tf32(areg[i].w));
        *(float4*)(As + srow[i] * AS_STRIDE + sk4[i] * 4) = cv;
    }

    // ---- accumulators init with bias ----
    float acc[8][4];
    #pragma unroll
    for (int nt = 0; nt < 8; nt++) {
        float b0 = bias[nt * 8 + 2 * tg];
        float b1 = bias[nt * 8 + 2 * tg + 1];
        acc[nt][0] = b0; acc[nt][1] = b1;
        acc[nt][2] = b0; acc[nt][3] = b1;
    }

    __syncthreads();

    // ---- issue As1 loads (agg) as a PURE batch (MLP=8); flight hides
    //      behind MMA0. No stores here (round-16 lesson). ----
    float* aggp = g_agg;
    #pragma unroll
    for (int i = 0; i < 8; i++) {
        float4 v = make_float4(0.f, 0.f, 0.f, 0.f);
        if (sok[i])
            v = *(const float4*)(aggp + (size_t)(rowbase + srow[i]) * 64 + sk4[i] * 4);
        areg[i] = v;
    }

    // ---- MMA h=0 (x_dst @ W_self^T) ----
    #pragma unroll
    for (int kc = 0; kc < 8; kc++) {
        const int k0 = kc * 8;
        const float* arow0 = As + (wr + g) * AS_STRIDE + k0;
        const float* arow1 = arow0 + 8 * AS_STRIDE;
        unsigned a0 = __float_as_uint(arow0[tg]);
        unsigned a1 = __float_as_uint(arow1[tg]);
        unsigned a2 = __float_as_uint(arow0[tg + 4]);
        unsigned a3 = __float_as_uint(arow1[tg + 4]);
        #pragma unroll
        for (int nt = 0; nt < 8; nt++) {
            const float* brow = Bs + (nt * 8 + g) * BS_STRIDE + k0;
            unsigned b0 = __float_as_uint(brow[tg]);
            unsigned b1 = __float_as_uint(brow[tg + 4]);
            MMA_TF32(acc[nt][0], acc[nt][1], acc[nt][2], acc[nt][3],
                     a0, a1, a2, a3, b0, b1);
        }
    }

    __syncthreads();   // all warps done reading As0

    // ---- store As1 to shared (cvt tf32) ----
    #pragma unroll
    for (int i = 0; i < 8; i++) {
        float4 cv;
        cv.x = __uint_as_float(f2tf32(areg[i].x));
        cv.y = __uint_as_float(f2tf32(areg[i].y));
        cv.z = __uint_as_float(f2tf32(areg[i].z));
        cv.w = __uint_as_float(f2tf32(areg[i].w));
        *(float4*)(As + srow[i] * AS_STRIDE + sk4[i] * 4) = cv;
    }
    __syncthreads();

    // ---- MMA h=1 (agg @ W_nei^T) ----
    #pragma unroll
    for (int kc = 0; kc < 8; kc++) {
        const int k0 = kc * 8;
        const float* arow0 = As + (wr + g) * AS_STRIDE + k0;
        const float* arow1 = arow0 + 8 * AS_STRIDE;
        unsigned a0 = __float_as_uint(arow0[tg]);
        unsigned a1 = __float_as_uint(arow1[tg]);
        unsigned a2 = __float_as_uint(arow0[tg + 4]);
        unsigned a3 = __float_as_uint(arow1[tg + 4]);
        #pragma unroll
        for (int nt = 0; nt < 8; nt++) {
            const float* brow = Bs + (nt * 8 + g) * BS_STRIDE + 64 + k0;
            unsigned b0 = __float_as_uint(brow[tg]);
            unsigned b1 = __float_as_uint(brow[tg + 4]);
            MMA_TF32(acc[nt][0], acc[nt][1], acc[nt][2], acc[nt][3],
                     a0, a1, a2, a3, b0, b1);
        }
    }

    // ---- output stores ----
    const int r0 = rowbase + wr + g;
    const int r1 = r0 + 8;
    if (r0 < N) {
        float* yrow = out + (size_t)r0 * 64;
        #pragma unroll
        for (int nt = 0; nt < 8; nt++)
            *(float2*)(yrow + nt * 8 + 2 * tg) = make_float2(acc[nt][0], acc[nt][1]);
    }
    if (r1 < N) {
        float* yrow = out + (size_t)r1 * 64;
        #pragma unroll
        for (int nt = 0; nt < 8; nt++)
            *(float2*)(yrow + nt * 8 + 2 * tg) = make_float2(acc[nt][2], acc[nt][3]);
    }

    // ---- EPILOGUE: re-zero the agg slots this thread consumed.
    //      Batched independent STG.128s after all compute; program order
    //      puts them after the As1 loads of the same addresses. ----
    const float4 z4 = make_float4(0.f, 0.f, 0.f, 0.f);
    #pragma unroll
    for (int i = 0; i < 8; i++) {
        if (sok[i])
            *(float4*)(aggp + (size_t)(rowbase + srow[i]) * 64 + sk4[i] * 4) = z4;
    }
}

// ---------------------------------------------------------------------------
// Inputs: 0:x_src f32[Ns*64] 1:x_dst f32[Nd*64] 2:edge_index[2E] (i32/i64)
//         3:edge_weight f32[E] 4:W_nei [64,64] 5:W_self [64,64] 6:b_self [64]
// Output: f32 [Nd*64]
// ---------------------------------------------------------------------------
extern "C" void kernel_launch(void* const* d_in, const int* in_sizes, int n_in,
                              void* d_out, int out_size)
{
    const float* x_src  = (const float*)d_in[0];
    const float* x_dst  = (const float*)d_in[1];
    const void*  ei     = d_in[2];
    const float* ew     = (const float*)d_in[3];
    const float* W_nei  = (const float*)d_in[4];
    const float* W_self = (const float*)d_in[5];
    const float* b_self = (const float*)d_in[6];
    float*       out    = (float*)d_out;

    const int n_src = in_sizes[0] / 64;
    const int n_dst = in_sizes[1] / 64;
    const int E     = in_sizes[3];

    static int smem_set = 0;
    if (!smem_set) {
        cudaFuncSetAttribute(fused_gemm_tf32_kernel,
                             cudaFuncAttributeMaxDynamicSharedMemorySize,
                             GEMM_SMEM_BYTES);
        smem_set = 1;
    }

    // 1) scatter (agg zeroed: module load on first call, GEMM epilogue after)
    {
        long long groups  = ((long long)E + 7) / 8;
        long long threads = groups * 16;
        int blocks = (int)((threads + 255) / 256);
        scatter_kernel<<<blocks, 256>>>(x_src, ei, ew, E, n_src);
    }

    // 2) fused tf32 GEMM (+ agg re-zero epilogue)
    fused_gemm_tf32_kernel<<<(n_dst + 127) / 128, 256, GEMM_SMEM_BYTES>>>(
        x_dst, W_self, W_nei, b_self, out, n_dst);
}